// round 14
// baseline (speedup 1.0000x reference)
#include <cuda_runtime.h>
#include <cstdint>
#include <cstddef>

// ---------------------------------------------------------------------------
// SNN forward:
//   GEMM1+pack: cur1 = data @ w1^T + b1 (R12 verbatim) -> LIF1 pattern bytes.
//   prep: per batch row, deterministic counting sort of active i by pattern
//         (R12 binning), bins PADDED to 4 entries with dummy idx=1024
//         (points at a zero SMEM row; +0.0f adds are RN-exact no-ops).
//   tail v7: 16 column-slices x 32 cols; each block pins its 128KB slice in
//         SMEM (plus zero row) -> hot loop is LDS-only, NO L2 traffic
//         (R12 was L2-capped: 14.2GB of w2t re-reads at ~52% L1 hit).
//         Warp = one row, lane = column; per-slice work-stealing counters.
//   combine: out[b] = (sum of 16 slice partials, fixed order)/T + b3.
// ---------------------------------------------------------------------------

static constexpr int BB  = 16384;
static constexpr int DIN = 512;
static constexpr int H0  = 1024;
static constexpr int H1  = 512;
static constexpr int T   = 8;
static constexpr int NSLICE = 16;          // H1/32
static constexpr int CHUNK  = 64;          // rows per steal
static constexpr int NCHUNK = BB / CHUNK;  // 256

// Scratch (device globals -- no runtime allocation allowed)
__device__ __align__(256) unsigned char g_pack[(size_t)BB * H0];        // 16 MB
__device__ __align__(256) float         g_w2t [(size_t)H0 * H1];        //  2 MB
__device__ __align__(256) uint16_t      g_idxlist[(size_t)BB * 2048];   // 64 MB
__device__ __align__(256) uint32_t      g_binmeta[(size_t)BB * 256];    // 16 MB
__device__ __align__(256) uint32_t      g_nbins[BB];
__device__ __align__(256) float         g_part[(size_t)NSLICE * BB];    //  1 MB
__device__                int           g_ctr[NSLICE];

// ===========================================================================
// GEMM1 + fused LIF1 pack (R12 verbatim -- bit-identical pack bytes)
// ===========================================================================
__global__ void __launch_bounds__(256) sgemm1_pack_kernel(
    const float* __restrict__ A,
    const float* __restrict__ W,
    const float* __restrict__ bias,
    unsigned char* __restrict__ pack,
    int M, int N, int K)
{
    __shared__ float As[2][16][128];
    __shared__ float Bs[2][16][128];

    const int tx = threadIdx.x;
    const int tm = tx >> 4;
    const int tn = tx & 15;

    const int m0 = blockIdx.y * 128;
    const int n0 = blockIdx.x * 128;

    const int f0 = tx;
    const int f1 = tx + 256;
    const int r0 = f0 >> 2, c40 = (f0 & 3) * 4;
    const int r1 = f1 >> 2, c41 = (f1 & 3) * 4;

    unsigned long long acc2[8][4];
#pragma unroll
    for (int i = 0; i < 8; ++i)
#pragma unroll
        for (int j = 0; j < 4; ++j) acc2[i][j] = 0ull;

    float4 ra0, ra1, rb0, rb1;

    auto load_regs = [&](int kt) {
        ra0 = *reinterpret_cast<const float4*>(&A[(size_t)(m0 + r0) * K + kt + c40]);
        ra1 = *reinterpret_cast<const float4*>(&A[(size_t)(m0 + r1) * K + kt + c41]);
        rb0 = *reinterpret_cast<const float4*>(&W[(size_t)(n0 + r0) * K + kt + c40]);
        rb1 = *reinterpret_cast<const float4*>(&W[(size_t)(n0 + r1) * K + kt + c41]);
    };
    auto store_smem = [&](int buf) {
        As[buf][c40 + 0][r0] = ra0.x;
        As[buf][c40 + 1][r0] = ra0.y;
        As[buf][c40 + 2][r0] = ra0.z;
        As[buf][c40 + 3][r0] = ra0.w;
        As[buf][c41 + 0][r1] = ra1.x;
        As[buf][c41 + 1][r1] = ra1.y;
        As[buf][c41 + 2][r1] = ra1.z;
        As[buf][c41 + 3][r1] = ra1.w;
        Bs[buf][c40 + 0][r0] = rb0.x;
        Bs[buf][c40 + 1][r0] = rb0.y;
        Bs[buf][c40 + 2][r0] = rb0.z;
        Bs[buf][c40 + 3][r0] = rb0.w;
        Bs[buf][c41 + 0][r1] = rb1.x;
        Bs[buf][c41 + 1][r1] = rb1.y;
        Bs[buf][c41 + 2][r1] = rb1.z;
        Bs[buf][c41 + 3][r1] = rb1.w;
    };

    load_regs(0);
    store_smem(0);
    __syncthreads();

    const int nt = K / 16;
    for (int it = 0; it < nt; ++it) {
        const int buf = it & 1;
        const bool more = (it + 1 < nt);
        if (more) load_regs((it + 1) * 16);

#pragma unroll
        for (int k = 0; k < 16; ++k) {
            float a[8];
            unsigned long long b2[4];
            *reinterpret_cast<float4*>(&a[0]) =
                *reinterpret_cast<const float4*>(&As[buf][k][tm * 8]);
            *reinterpret_cast<float4*>(&a[4]) =
                *reinterpret_cast<const float4*>(&As[buf][k][tm * 8 + 4]);
            *reinterpret_cast<float4*>(&b2[0]) =
                *reinterpret_cast<const float4*>(&Bs[buf][k][tn * 8]);
            *reinterpret_cast<float4*>(&b2[2]) =
                *reinterpret_cast<const float4*>(&Bs[buf][k][tn * 8 + 4]);
#pragma unroll
            for (int i = 0; i < 8; ++i) {
                unsigned long long a2;
                asm("mov.b64 %0, {%1, %1};" : "=l"(a2) : "f"(a[i]));
#pragma unroll
                for (int j = 0; j < 4; ++j)
                    asm("fma.rn.f32x2 %0, %1, %2, %0;"
                        : "+l"(acc2[i][j]) : "l"(a2), "l"(b2[j]));
            }
        }

        if (more) {
            store_smem(buf ^ 1);
            __syncthreads();
        }
    }

    float bj[8];
    const int gn0 = n0 + tn * 8;
#pragma unroll
    for (int j = 0; j < 8; ++j) bj[j] = __ldg(&bias[gn0 + j]);

#pragma unroll
    for (int i = 0; i < 8; ++i) {
        const int gm = m0 + tm * 8 + i;
        float accf[8];
#pragma unroll
        for (int j = 0; j < 4; ++j)
            asm("mov.b64 {%0, %1}, %2;"
                : "=f"(accf[2 * j]), "=f"(accf[2 * j + 1]) : "l"(acc2[i][j]));

        unsigned long long u = 0ull;
#pragma unroll
        for (int j = 0; j < 8; ++j) {
            const float c = accf[j] + bj[j];
            float mem = 0.0f;
            unsigned p = 0;
#pragma unroll
            for (int t = 0; t < T; ++t) {
                const float reset = (mem > 1.0f) ? 1.0f : 0.0f;   // OLD mem
                mem = mem + c - reset;                             // beta1 = 1.0
                p |= ((mem - 1.0f) > 0.0f ? 1u : 0u) << t;
            }
            u |= (unsigned long long)p << (8 * j);
        }
        *reinterpret_cast<unsigned long long*>(&pack[(size_t)gm * N + gn0]) = u;
    }
}

// ===========================================================================
// Transpose w2 [H1][H0] -> w2t [H0][H1]
// ===========================================================================
__global__ void transpose_w2_kernel(const float* __restrict__ w2,
                                    float* __restrict__ w2t)
{
    __shared__ float tile[32][33];
    const int bx = blockIdx.x * 32;
    const int by = blockIdx.y * 32;
    const int tx = threadIdx.x, ty = threadIdx.y;
#pragma unroll
    for (int j = 0; j < 32; j += 8)
        tile[ty + j][tx] = w2[(size_t)(by + ty + j) * H0 + bx + tx];
    __syncthreads();
#pragma unroll
    for (int j = 0; j < 32; j += 8)
        w2t[(size_t)(bx + ty + j) * H1 + by + tx] = tile[tx][ty + j];
}

// ===========================================================================
// Prep: per batch row, R12 binning -> padded (mult-of-4) idx list + bin meta.
// Dummy entries = 1024 (zero SMEM row in the tail). Deterministic order.
// meta = (pattern<<22) | (paddedStart<<11) | paddedCount
// ===========================================================================
__global__ void __launch_bounds__(128) prep_kernel(
    const unsigned char* __restrict__ pack,
    uint16_t* __restrict__ idxlist,
    uint32_t* __restrict__ binmeta,
    uint32_t* __restrict__ nbins_out)
{
    __shared__ uint32_t s_idx32[1024];    // 2048 u16
    __shared__ int      s_start[256];
    __shared__ int      s_wbase[4][256];
    __shared__ uint32_t s_meta[256];
    __shared__ int      s_w4a[4], s_w4b[4];
    __shared__ int      s_nbins;

    const int b    = blockIdx.x;
    const int tid  = threadIdx.x;
    const int lane = tid & 31;
    const int wid  = tid >> 5;
    const unsigned FULL = 0xFFFFFFFFu;

    const uint2 wd =
        reinterpret_cast<const uint2*>(pack)[(size_t)b * (H0 / 8) + tid];
    uint32_t bytes[8];
#pragma unroll
    for (int j = 0; j < 4; ++j) {
        bytes[j]     = (wd.x >> (8 * j)) & 255u;
        bytes[4 + j] = (wd.y >> (8 * j)) & 255u;
    }

#pragma unroll
    for (int k = 0; k < 8; ++k) s_wbase[(tid * 8 + k) >> 8][(tid * 8 + k) & 255] = 0;
    // prefill idx list with dummy 1024 (0x0400)
#pragma unroll
    for (int k = 0; k < 8; ++k) s_idx32[tid * 8 + k] = 0x04000400u;
    __syncthreads();

#pragma unroll
    for (int j = 0; j < 8; ++j)
        if (bytes[j]) atomicAdd(&s_wbase[wid][bytes[j]], 1);
    __syncthreads();

    const int p0 = tid * 2, p1 = tid * 2 + 1;
    const int v0 = s_wbase[0][p0] + s_wbase[1][p0] + s_wbase[2][p0] + s_wbase[3][p0];
    const int v1 = s_wbase[0][p1] + s_wbase[1][p1] + s_wbase[2][p1] + s_wbase[3][p1];
    const int v0p = (v0 + 3) & ~3;
    const int v1p = (v1 + 3) & ~3;

    int e0;
    {
        int inc = v0p + v1p;
#pragma unroll
        for (int d = 1; d < 32; d <<= 1) {
            const int t = __shfl_up_sync(FULL, inc, d);
            if (lane >= d) inc += t;
        }
        if (lane == 31) s_w4a[wid] = inc;
        __syncthreads();
        int woff = 0;
#pragma unroll
        for (int w = 0; w < 4; ++w) woff += (w < wid) ? s_w4a[w] : 0;
        e0 = woff + inc - (v0p + v1p);
        s_start[p0] = e0;
        s_start[p1] = e0 + v0p;
    }

    // compact nonempty pattern metas (exclude pattern 0)
    {
        const int f0 = (p0 != 0 && v0 > 0) ? 1 : 0;
        const int f1 = (v1 > 0) ? 1 : 0;
        int inc = f0 + f1;
#pragma unroll
        for (int d = 1; d < 32; d <<= 1) {
            const int t = __shfl_up_sync(FULL, inc, d);
            if (lane >= d) inc += t;
        }
        if (lane == 31) s_w4b[wid] = inc;
        __syncthreads();
        int woff = 0;
#pragma unroll
        for (int w = 0; w < 4; ++w) woff += (w < wid) ? s_w4b[w] : 0;
        const int c0 = woff + inc - (f0 + f1);
        if (f0) s_meta[c0] =
            ((uint32_t)p0 << 22) | ((uint32_t)e0 << 11) | (uint32_t)v0p;
        if (f1) s_meta[c0 + f0] =
            ((uint32_t)p1 << 22) | ((uint32_t)(e0 + v0p) << 11) | (uint32_t)v1p;
        if (tid == 127) s_nbins = c0 + f0 + f1;
    }
    __syncthreads();

    // histogram -> per-warp cursors (padded starts, real counts)
    {
#pragma unroll
        for (int pp = 0; pp < 2; ++pp) {
            const int p = tid * 2 + pp;
            int run = s_start[p];
#pragma unroll
            for (int w = 0; w < 4; ++w) {
                const int t = s_wbase[w][p];
                s_wbase[w][p] = run;
                run += t;
            }
        }
    }
    __syncthreads();

    // deterministic scatter (dummies remain in the padding gaps)
    uint16_t* s_idx16 = reinterpret_cast<uint16_t*>(s_idx32);
#pragma unroll
    for (int j = 0; j < 8; ++j) {
        const uint32_t bj = bytes[j];
        const uint32_t grp = __match_any_sync(FULL, bj);
        const int leader = __ffs(grp) - 1;
        int base = 0;
        if (bj && lane == leader)
            base = atomicAdd(&s_wbase[wid][bj], __popc(grp));
        base = __shfl_sync(FULL, base, leader);
        if (bj) {
            const int pos = base + __popc(grp & ((1u << lane) - 1u));
            s_idx16[pos] = (uint16_t)(tid * 8 + j);
        }
    }
    __syncthreads();

    // write out
    const int nb = s_nbins;
    if (tid == 0) nbins_out[b] = (uint32_t)nb;
    for (int k = tid; k < 256; k += 128)
        binmeta[(size_t)b * 256 + k] = (k < nb) ? s_meta[k] : 0u;
    uint32_t* dstl = reinterpret_cast<uint32_t*>(idxlist + (size_t)b * 2048);
#pragma unroll
    for (int k = 0; k < 8; ++k)
        dstl[tid * 8 + k] = s_idx32[tid * 8 + k];
}

// ===========================================================================
// ctr init
// ===========================================================================
__global__ void ctr_init_kernel()
{
    if (threadIdx.x < NSLICE) g_ctr[threadIdx.x] = 0;
}

// ===========================================================================
// Tail v7: slice-resident accumulation. Block pins 32 cols x 1025 rows of
// w2t in SMEM (row 1024 = zeros for padding dummies). Warp = one batch row,
// lane = column. Work stealing per slice. Per-column arithmetic == R12.
// ===========================================================================
__global__ void __launch_bounds__(256) snn_slice_kernel(
    const float* __restrict__ w2t,
    const uint16_t* __restrict__ idxlist,
    const uint32_t* __restrict__ binmeta,
    const uint32_t* __restrict__ nbins_in,
    const float* __restrict__ b2,
    const float* __restrict__ w3,
    float* __restrict__ part)
{
    extern __shared__ float slice[];          // [1025][32]
    __shared__ int s_chunk;

    const int sid  = blockIdx.x;              // 0..15
    const int c0   = sid * 32;
    const int tid  = threadIdx.x;
    const int lane = tid & 31;
    const int wid  = tid >> 5;                // 0..7
    const unsigned FULL = 0xFFFFFFFFu;

    // stage slice (coalesced: warp reads 128B per row)
    for (int r = wid; r < 1024; r += 8)
        slice[r * 32 + lane] = w2t[(size_t)r * H1 + c0 + lane];
    if (wid == 0) slice[1024 * 32 + lane] = 0.0f;

    const float b2v = __ldg(&b2[c0 + lane]);
    const float w3v = __ldg(&w3[c0 + lane]);
    __syncthreads();

    for (;;) {
        if (tid == 0) s_chunk = atomicAdd(&g_ctr[sid], 1);
        __syncthreads();
        const int chunk = s_chunk;
        __syncthreads();                      // s_chunk stable before reuse
        if (chunk >= NCHUNK) break;
        const int rowbase = chunk * CHUNK;

        for (int j = 0; j < CHUNK / 8; ++j) {
            const int row = rowbase + wid * (CHUNK / 8) + j;

            const int nb = __ldg(&nbins_in[row]);
            const uint32_t* meta = binmeta + (size_t)row * 256;
            const uint16_t* list = idxlist + (size_t)row * 2048;

            float acc[T];
#pragma unroll
            for (int t = 0; t < T; ++t) acc[t] = 0.0f;

            for (int bi = 0; bi < nb; ++bi) {
                const uint32_t m = __ldg(&meta[bi]);
                const int pat  = (int)(m >> 22);
                const int st   = (int)((m >> 11) & 0x7FF);
                const int g4   = (int)(m & 0x7FF) >> 2;
                const unsigned long long* q =
                    reinterpret_cast<const unsigned long long*>(list + st);

                float rs = 0.0f;
#pragma unroll 2
                for (int g = 0; g < g4; ++g) {
                    const unsigned long long v = __ldg(&q[g]);
                    const int i0 = (int)(v & 0xFFFFu);
                    const int i1 = (int)((v >> 16) & 0xFFFFu);
                    const int i2 = (int)((v >> 32) & 0xFFFFu);
                    const int i3 = (int)(v >> 48);
                    const float a0 = slice[i0 * 32 + lane];
                    const float a1 = slice[i1 * 32 + lane];
                    const float a2 = slice[i2 * 32 + lane];
                    const float a3 = slice[i3 * 32 + lane];
                    rs += a0;                 // dummies add +0.0f (exact)
                    rs += a1;
                    rs += a2;
                    rs += a3;
                }

#pragma unroll
                for (int t = 0; t < T; ++t)
                    asm("{ .reg .pred q;\n\t"
                        "setp.ne.u32 q, %2, 0;\n\t"
                        "@q add.rn.f32 %0, %0, %1; }"
                        : "+f"(acc[t])
                        : "f"(rs), "r"((unsigned)pat & (1u << t)));
            }

            // LIF2 + w3 partial (this warp's 32 cols)
            float mem = 0.0f, ao = 0.0f;
#pragma unroll
            for (int t = 0; t < T; ++t) {
                const float c = acc[t] + b2v;
                const float r = (mem > 1.0f) ? 1.0f : 0.0f;   // OLD mem
                mem = 0.95f * mem + c - r;
                ao += ((mem - 1.0f) > 0.0f) ? w3v : 0.0f;
            }
#pragma unroll
            for (int d = 16; d > 0; d >>= 1)
                ao += __shfl_down_sync(FULL, ao, d);
            if (lane == 0) part[(size_t)sid * BB + row] = ao;
        }
    }
}

// ===========================================================================
// Combine 16 slice partials (fixed ascending order -> deterministic)
// ===========================================================================
__global__ void combine_out_kernel(const float* __restrict__ part,
                                   const float* __restrict__ b3,
                                   float* __restrict__ out)
{
    const int b = blockIdx.x * blockDim.x + threadIdx.x;
    if (b >= BB) return;
    float s = 0.0f;
#pragma unroll
    for (int k = 0; k < NSLICE; ++k) s += part[(size_t)k * BB + b];
    out[b] = s * (1.0f / T) + __ldg(&b3[0]);
}

// ---------------------------------------------------------------------------
extern "C" void kernel_launch(void* const* d_in, const int* in_sizes, int n_in,
                              void* d_out, int out_size)
{
    const float* data = (const float*)d_in[0];
    const float* w1   = (const float*)d_in[1];
    const float* b1   = (const float*)d_in[2];
    const float* w2   = (const float*)d_in[3];
    const float* b2   = (const float*)d_in[4];
    const float* w3   = (const float*)d_in[5];
    const float* b3   = (const float*)d_in[6];
    float* out = (float*)d_out;

    unsigned char* pack;
    float *w2t, *part;
    uint16_t* idxl;
    uint32_t *bmeta, *nb;
    cudaGetSymbolAddress((void**)&pack,  g_pack);
    cudaGetSymbolAddress((void**)&w2t,   g_w2t);
    cudaGetSymbolAddress((void**)&part,  g_part);
    cudaGetSymbolAddress((void**)&idxl,  g_idxlist);
    cudaGetSymbolAddress((void**)&bmeta, g_binmeta);
    cudaGetSymbolAddress((void**)&nb,    g_nbins);

    const int slice_smem = 1025 * 32 * 4;   // 131200 B
    cudaFuncSetAttribute(snn_slice_kernel,
                         cudaFuncAttributeMaxDynamicSharedMemorySize, slice_smem);

    // 1) transpose w2 -> w2t [H0][H1]
    {
        dim3 grid(H0 / 32, H1 / 32);
        transpose_w2_kernel<<<grid, dim3(32, 8)>>>(w2, w2t);
    }

    // 2) GEMM1 + fused LIF1 pack
    {
        dim3 grid(H0 / 128, BB / 128);
        sgemm1_pack_kernel<<<grid, 256>>>(data, w1, b1, pack, BB, H0, DIN);
    }

    // 3) prep: padded bin lists per row
    prep_kernel<<<BB, 128>>>(pack, idxl, bmeta, nb);

    // 4) work-steal counters
    ctr_init_kernel<<<1, 32>>>();

    // 5) slice tail (16 slices x 9 blocks = 144 blocks, 1 wave)
    {
        dim3 grid(NSLICE, 9);
        snn_slice_kernel<<<grid, 256, slice_smem>>>(
            w2t, idxl, bmeta, nb, b2, w3, part);
    }

    // 6) combine partials -> out
    combine_out_kernel<<<(BB + 255) / 256, 256>>>(part, b3, out);
}

// round 15
// speedup vs baseline: 2.9249x; 2.9249x over previous
#include <cuda_runtime.h>
#include <cstdint>
#include <cstddef>

// ---------------------------------------------------------------------------
// SNN forward (R12 skeleton -- best known: 1059us):
//   GEMM1+pack: cur1 = data @ w1^T + b1 (double-buffered SIMT fp32;
//     R1-identical arithmetic) -> LIF1 pattern bytes, cur1 never stored.
//   tail v8 = R12 tail with occupancy push: __launch_bounds__(128,8)
//     (64-reg cap -> 8 blocks/SM vs ~6) and unroll-3 prefetch (6 u64 temps,
//     fits the cap without hot-loop spills; aggregate per-SM MLP unchanged).
//     Adds stay k-ascending -> bit-identical sums (expect rel_err 1.16694e-7).
//   R13/R14 lessons: keep block-per-row + LDG.128/thread; no control-flow
//     duplication per unit of reuse.
// ---------------------------------------------------------------------------

static constexpr int BB  = 16384;
static constexpr int DIN = 512;
static constexpr int H0  = 1024;
static constexpr int H1  = 512;
static constexpr int T   = 8;

// Scratch (device globals -- no runtime allocation allowed)
__device__ __align__(256) unsigned char g_pack[(size_t)BB * H0];  // 16 MB
__device__ __align__(256) float         g_w2t [(size_t)H0 * H1]; //  2 MB

// ===========================================================================
// GEMM1 + fused LIF1 pack (R12 verbatim -- bit-identical pack bytes)
// ===========================================================================
__global__ void __launch_bounds__(256) sgemm1_pack_kernel(
    const float* __restrict__ A,
    const float* __restrict__ W,
    const float* __restrict__ bias,
    unsigned char* __restrict__ pack,
    int M, int N, int K)
{
    __shared__ float As[2][16][128];
    __shared__ float Bs[2][16][128];

    const int tx = threadIdx.x;
    const int tm = tx >> 4;
    const int tn = tx & 15;

    const int m0 = blockIdx.y * 128;
    const int n0 = blockIdx.x * 128;

    const int f0 = tx;
    const int f1 = tx + 256;
    const int r0 = f0 >> 2, c40 = (f0 & 3) * 4;
    const int r1 = f1 >> 2, c41 = (f1 & 3) * 4;

    unsigned long long acc2[8][4];
#pragma unroll
    for (int i = 0; i < 8; ++i)
#pragma unroll
        for (int j = 0; j < 4; ++j) acc2[i][j] = 0ull;

    float4 ra0, ra1, rb0, rb1;

    auto load_regs = [&](int kt) {
        ra0 = *reinterpret_cast<const float4*>(&A[(size_t)(m0 + r0) * K + kt + c40]);
        ra1 = *reinterpret_cast<const float4*>(&A[(size_t)(m0 + r1) * K + kt + c41]);
        rb0 = *reinterpret_cast<const float4*>(&W[(size_t)(n0 + r0) * K + kt + c40]);
        rb1 = *reinterpret_cast<const float4*>(&W[(size_t)(n0 + r1) * K + kt + c41]);
    };
    auto store_smem = [&](int buf) {
        As[buf][c40 + 0][r0] = ra0.x;
        As[buf][c40 + 1][r0] = ra0.y;
        As[buf][c40 + 2][r0] = ra0.z;
        As[buf][c40 + 3][r0] = ra0.w;
        As[buf][c41 + 0][r1] = ra1.x;
        As[buf][c41 + 1][r1] = ra1.y;
        As[buf][c41 + 2][r1] = ra1.z;
        As[buf][c41 + 3][r1] = ra1.w;
        Bs[buf][c40 + 0][r0] = rb0.x;
        Bs[buf][c40 + 1][r0] = rb0.y;
        Bs[buf][c40 + 2][r0] = rb0.z;
        Bs[buf][c40 + 3][r0] = rb0.w;
        Bs[buf][c41 + 0][r1] = rb1.x;
        Bs[buf][c41 + 1][r1] = rb1.y;
        Bs[buf][c41 + 2][r1] = rb1.z;
        Bs[buf][c41 + 3][r1] = rb1.w;
    };

    load_regs(0);
    store_smem(0);
    __syncthreads();

    const int nt = K / 16;
    for (int it = 0; it < nt; ++it) {
        const int buf = it & 1;
        const bool more = (it + 1 < nt);
        if (more) load_regs((it + 1) * 16);

#pragma unroll
        for (int k = 0; k < 16; ++k) {
            float a[8];
            unsigned long long b2[4];
            *reinterpret_cast<float4*>(&a[0]) =
                *reinterpret_cast<const float4*>(&As[buf][k][tm * 8]);
            *reinterpret_cast<float4*>(&a[4]) =
                *reinterpret_cast<const float4*>(&As[buf][k][tm * 8 + 4]);
            *reinterpret_cast<float4*>(&b2[0]) =
                *reinterpret_cast<const float4*>(&Bs[buf][k][tn * 8]);
            *reinterpret_cast<float4*>(&b2[2]) =
                *reinterpret_cast<const float4*>(&Bs[buf][k][tn * 8 + 4]);
#pragma unroll
            for (int i = 0; i < 8; ++i) {
                unsigned long long a2;
                asm("mov.b64 %0, {%1, %1};" : "=l"(a2) : "f"(a[i]));
#pragma unroll
                for (int j = 0; j < 4; ++j)
                    asm("fma.rn.f32x2 %0, %1, %2, %0;"
                        : "+l"(acc2[i][j]) : "l"(a2), "l"(b2[j]));
            }
        }

        if (more) {
            store_smem(buf ^ 1);
            __syncthreads();
        }
    }

    float bj[8];
    const int gn0 = n0 + tn * 8;
#pragma unroll
    for (int j = 0; j < 8; ++j) bj[j] = __ldg(&bias[gn0 + j]);

#pragma unroll
    for (int i = 0; i < 8; ++i) {
        const int gm = m0 + tm * 8 + i;
        float accf[8];
#pragma unroll
        for (int j = 0; j < 4; ++j)
            asm("mov.b64 {%0, %1}, %2;"
                : "=f"(accf[2 * j]), "=f"(accf[2 * j + 1]) : "l"(acc2[i][j]));

        unsigned long long u = 0ull;
#pragma unroll
        for (int j = 0; j < 8; ++j) {
            const float c = accf[j] + bj[j];
            float mem = 0.0f;
            unsigned p = 0;
#pragma unroll
            for (int t = 0; t < T; ++t) {
                const float reset = (mem > 1.0f) ? 1.0f : 0.0f;   // OLD mem
                mem = mem + c - reset;                             // beta1 = 1.0
                p |= ((mem - 1.0f) > 0.0f ? 1u : 0u) << t;
            }
            u |= (unsigned long long)p << (8 * j);
        }
        *reinterpret_cast<unsigned long long*>(&pack[(size_t)gm * N + gn0]) = u;
    }
}

// ===========================================================================
// Transpose w2 [H1][H0] -> w2t [H0][H1]
// ===========================================================================
__global__ void transpose_w2_kernel(const float* __restrict__ w2,
                                    float* __restrict__ w2t)
{
    __shared__ float tile[32][33];
    const int bx = blockIdx.x * 32;
    const int by = blockIdx.y * 32;
    const int tx = threadIdx.x, ty = threadIdx.y;
#pragma unroll
    for (int j = 0; j < 32; j += 8)
        tile[ty + j][tx] = w2[(size_t)(by + ty + j) * H0 + bx + tx];
    __syncthreads();
#pragma unroll
    for (int j = 0; j < 32; j += 8)
        w2t[(size_t)(bx + ty + j) * H1 + by + tx] = tile[tx][ty + j];
}

// ===========================================================================
// Fused tail v8: 128 threads, thread owns 4 cols (LDG.128), block per row.
// Binning identical to R12. Bin loop unroll-3 (MLP 3), adds k-ascending.
// __launch_bounds__(128, 8): 64-reg cap -> 8 blocks/SM.
// ===========================================================================
__global__ void __launch_bounds__(128, 8) snn_tail_kernel(
    const unsigned char* __restrict__ pack,   // [BB][H0]
    const float* __restrict__ w2t,            // [H0][H1]
    const float* __restrict__ b2,
    const float* __restrict__ w3,
    const float* __restrict__ b3,
    float* __restrict__ out)
{
    __shared__ uint16_t s_idx[H0];
    __shared__ int      s_cnt[256];
    __shared__ int      s_start[256];
    __shared__ int      s_wbase[4][256];
    __shared__ int      s_binlist[256];
    __shared__ int      s_w4a[4], s_w4b[4];
    __shared__ int      s_nbins;
    __shared__ float    s_red[4];

    const int b    = blockIdx.x;
    const int tid  = threadIdx.x;
    const int lane = tid & 31;
    const int wid  = tid >> 5;
    const unsigned FULL = 0xFFFFFFFFu;

    const uint2 wd =
        reinterpret_cast<const uint2*>(pack)[(size_t)b * (H0 / 8) + tid];
    uint32_t bytes[8];
#pragma unroll
    for (int j = 0; j < 4; ++j) {
        bytes[j]     = (wd.x >> (8 * j)) & 255u;
        bytes[4 + j] = (wd.y >> (8 * j)) & 255u;
    }

#pragma unroll
    for (int k = 0; k < 8; ++k) s_wbase[(tid * 8 + k) >> 8][(tid * 8 + k) & 255] = 0;
    __syncthreads();

#pragma unroll
    for (int j = 0; j < 8; ++j)
        if (bytes[j]) atomicAdd(&s_wbase[wid][bytes[j]], 1);
    __syncthreads();

    const int p0 = tid * 2, p1 = tid * 2 + 1;
    const int v0 = s_wbase[0][p0] + s_wbase[1][p0] + s_wbase[2][p0] + s_wbase[3][p0];
    const int v1 = s_wbase[0][p1] + s_wbase[1][p1] + s_wbase[2][p1] + s_wbase[3][p1];

    {
        int inc = v0 + v1;
#pragma unroll
        for (int d = 1; d < 32; d <<= 1) {
            const int t = __shfl_up_sync(FULL, inc, d);
            if (lane >= d) inc += t;
        }
        if (lane == 31) s_w4a[wid] = inc;
        __syncthreads();
        int woff = 0;
#pragma unroll
        for (int w = 0; w < 4; ++w) woff += (w < wid) ? s_w4a[w] : 0;
        const int e0 = woff + inc - (v0 + v1);
        s_start[p0] = e0;
        s_start[p1] = e0 + v0;
        s_cnt[p0] = v0;
        s_cnt[p1] = v1;
    }

    {
        const int f0 = (p0 != 0 && v0 > 0) ? 1 : 0;
        const int f1 = (v1 > 0) ? 1 : 0;
        int inc = f0 + f1;
#pragma unroll
        for (int d = 1; d < 32; d <<= 1) {
            const int t = __shfl_up_sync(FULL, inc, d);
            if (lane >= d) inc += t;
        }
        if (lane == 31) s_w4b[wid] = inc;
        __syncthreads();
        int woff = 0;
#pragma unroll
        for (int w = 0; w < 4; ++w) woff += (w < wid) ? s_w4b[w] : 0;
        const int c0 = woff + inc - (f0 + f1);
        if (f0) s_binlist[c0] = p0;
        if (f1) s_binlist[c0 + f0] = p1;
        if (tid == 127) s_nbins = c0 + f0 + f1;
    }
    __syncthreads();

    {
#pragma unroll
        for (int pp = 0; pp < 2; ++pp) {
            const int p = tid * 2 + pp;
            int run = s_start[p];
#pragma unroll
            for (int w = 0; w < 4; ++w) {
                const int t = s_wbase[w][p];
                s_wbase[w][p] = run;
                run += t;
            }
        }
    }
    __syncthreads();

#pragma unroll
    for (int j = 0; j < 8; ++j) {
        const uint32_t bj = bytes[j];
        const uint32_t grp = __match_any_sync(FULL, bj);
        const int leader = __ffs(grp) - 1;
        int base = 0;
        if (bj && lane == leader)
            base = atomicAdd(&s_wbase[wid][bj], __popc(grp));
        base = __shfl_sync(FULL, base, leader);
        if (bj) {
            const int pos = base + __popc(grp & ((1u << lane) - 1u));
            s_idx[pos] = (uint16_t)(tid * 8 + j);
        }
    }
    __syncthreads();

    unsigned long long acc[T][2];
#pragma unroll
    for (int t = 0; t < T; ++t) { acc[t][0] = 0ull; acc[t][1] = 0ull; }

    const char* wbase = reinterpret_cast<const char*>(w2t) + tid * 16;
    const int nbins = s_nbins;

    for (int bi = 0; bi < nbins; ++bi) {
        const int p  = s_binlist[bi];
        const int st = s_start[p];
        const int en = st + s_cnt[p];

        unsigned long long rs0 = 0ull, rs1 = 0ull;
        int k = st;
        // unroll-3: 3 independent LDG.128 in flight, adds in strict k order
        for (; k + 3 <= en; k += 3) {
            const uint32_t i0 = s_idx[k];
            const uint32_t i1 = s_idx[k + 1];
            const uint32_t i2 = s_idx[k + 2];
            unsigned long long a0, b0, a1, b1, a2, b2;
            asm("ld.global.nc.L1::evict_last.v2.u64 {%0, %1}, [%2];"
                : "=l"(a0), "=l"(b0) : "l"(wbase + (size_t)i0 * (H1 * 4)));
            asm("ld.global.nc.L1::evict_last.v2.u64 {%0, %1}, [%2];"
                : "=l"(a1), "=l"(b1) : "l"(wbase + (size_t)i1 * (H1 * 4)));
            asm("ld.global.nc.L1::evict_last.v2.u64 {%0, %1}, [%2];"
                : "=l"(a2), "=l"(b2) : "l"(wbase + (size_t)i2 * (H1 * 4)));
            asm("add.rn.f32x2 %0, %0, %1;" : "+l"(rs0) : "l"(a0));
            asm("add.rn.f32x2 %0, %0, %1;" : "+l"(rs1) : "l"(b0));
            asm("add.rn.f32x2 %0, %0, %1;" : "+l"(rs0) : "l"(a1));
            asm("add.rn.f32x2 %0, %0, %1;" : "+l"(rs1) : "l"(b1));
            asm("add.rn.f32x2 %0, %0, %1;" : "+l"(rs0) : "l"(a2));
            asm("add.rn.f32x2 %0, %0, %1;" : "+l"(rs1) : "l"(b2));
        }
        for (; k < en; ++k) {
            const uint32_t i = s_idx[k];
            unsigned long long w01, w23;
            asm("ld.global.nc.L1::evict_last.v2.u64 {%0, %1}, [%2];"
                : "=l"(w01), "=l"(w23)
                : "l"(wbase + (size_t)i * (H1 * 4)));
            asm("add.rn.f32x2 %0, %0, %1;" : "+l"(rs0) : "l"(w01));
            asm("add.rn.f32x2 %0, %0, %1;" : "+l"(rs1) : "l"(w23));
        }

#pragma unroll
        for (int t = 0; t < T; ++t) {
            asm("{ .reg .pred q;\n\t"
                "setp.ne.u32 q, %4, 0;\n\t"
                "@q add.rn.f32x2 %0, %0, %2;\n\t"
                "@q add.rn.f32x2 %1, %1, %3; }"
                : "+l"(acc[t][0]), "+l"(acc[t][1])
                : "l"(rs0), "l"(rs1), "r"((unsigned)p & (1u << t)));
        }
    }

    const int n0 = tid * 4;
    const float4 b2v = *reinterpret_cast<const float4*>(b2 + n0);
    const float4 w3v = *reinterpret_cast<const float4*>(w3 + n0);
    float m0 = 0.0f, m1 = 0.0f, m2 = 0.0f, m3 = 0.0f, aout = 0.0f;
#pragma unroll
    for (int t = 0; t < T; ++t) {
        float a0, a1, a2, a3;
        asm("mov.b64 {%0, %1}, %2;" : "=f"(a0), "=f"(a1) : "l"(acc[t][0]));
        asm("mov.b64 {%0, %1}, %2;" : "=f"(a2), "=f"(a3) : "l"(acc[t][1]));
        const float c0 = a0 + b2v.x, c1 = a1 + b2v.y;
        const float c2 = a2 + b2v.z, c3 = a3 + b2v.w;
        const float r0 = (m0 > 1.0f) ? 1.0f : 0.0f;   // reset on OLD mem
        const float r1 = (m1 > 1.0f) ? 1.0f : 0.0f;
        const float r2 = (m2 > 1.0f) ? 1.0f : 0.0f;
        const float r3 = (m3 > 1.0f) ? 1.0f : 0.0f;
        m0 = 0.95f * m0 + c0 - r0;
        m1 = 0.95f * m1 + c1 - r1;
        m2 = 0.95f * m2 + c2 - r2;
        m3 = 0.95f * m3 + c3 - r3;
        aout += ((m0 - 1.0f) > 0.0f) ? w3v.x : 0.0f;
        aout += ((m1 - 1.0f) > 0.0f) ? w3v.y : 0.0f;
        aout += ((m2 - 1.0f) > 0.0f) ? w3v.z : 0.0f;
        aout += ((m3 - 1.0f) > 0.0f) ? w3v.w : 0.0f;
    }

#pragma unroll
    for (int d = 16; d > 0; d >>= 1)
        aout += __shfl_down_sync(FULL, aout, d);
    if (lane == 0) s_red[wid] = aout;
    __syncthreads();
    if (tid == 0) {
        out[b] = (s_red[0] + s_red[1] + s_red[2] + s_red[3]) * (1.0f / T)
               + __ldg(&b3[0]);
    }
}

// ---------------------------------------------------------------------------
extern "C" void kernel_launch(void* const* d_in, const int* in_sizes, int n_in,
                              void* d_out, int out_size)
{
    const float* data = (const float*)d_in[0];
    const float* w1   = (const float*)d_in[1];
    const float* b1   = (const float*)d_in[2];
    const float* w2   = (const float*)d_in[3];
    const float* b2   = (const float*)d_in[4];
    const float* w3   = (const float*)d_in[5];
    const float* b3   = (const float*)d_in[6];
    float* out = (float*)d_out;

    unsigned char* pack;
    float* w2t;
    cudaGetSymbolAddress((void**)&pack, g_pack);
    cudaGetSymbolAddress((void**)&w2t,  g_w2t);

    // 1) transpose w2 -> w2t [H0][H1]
    {
        dim3 grid(H0 / 32, H1 / 32);     // (32, 16)
        transpose_w2_kernel<<<grid, dim3(32, 8)>>>(w2, w2t);
    }

    // 2) GEMM1 + fused LIF1 pack (cur1 never materialized)
    {
        dim3 grid(H0 / 128, BB / 128);   // (8, 128)
        sgemm1_pack_kernel<<<grid, 256>>>(data, w1, b1, pack, BB, H0, DIN);
    }

    // 3) fused sparse layer-2 + LIF2 + output head
    snn_tail_kernel<<<BB, 128>>>(pack, w2t, b2, w3, b3, out);
}

// round 16
// speedup vs baseline: 2.9398x; 1.0051x over previous
#include <cuda_runtime.h>
#include <cstdint>
#include <cstddef>

// ---------------------------------------------------------------------------
// SNN forward, fused producer/consumer (overlap GEMM's FMA-bound phase with
// the tail's L2-bound phase in ONE kernel):
//   blocks [0, 4096):  GEMM1 64x64 tiles + LIF1 pack epilogue
//                      (per-element k-sequential FMA chain == R12 -> cur1,
//                       pack bytes bit-identical to R12)
//   blocks [4096, ...): R12 tail verbatim (binning + unroll-4 run sums),
//                      gated per 64-row mtile by device flags
//   flag protocol: producer: fence -> barrier -> atomicAdd(flag[mtile]);
//                  consumer: acquire-load spin + __nanosleep. CTAs dispatch
//                  in bid order -> producers always precede consumers.
// ---------------------------------------------------------------------------

static constexpr int BB  = 16384;
static constexpr int DIN = 512;
static constexpr int H0  = 1024;
static constexpr int H1  = 512;
static constexpr int T   = 8;

static constexpr int NMT      = 256;              // mtiles of 64 rows
static constexpr int NTILE    = 16;               // 64-col tiles in H0
static constexpr int NGEMM    = NMT * NTILE;      // 4096 producer blocks
static constexpr int SMEM_DYN = 9728;             // max(gemm 8KB, tail ~9.3KB)

// Scratch (device globals -- no runtime allocation allowed)
__device__ __align__(256) unsigned char g_pack[(size_t)BB * H0];  // 16 MB
__device__ __align__(256) float         g_w2t [(size_t)H0 * H1]; //  2 MB
__device__                int           g_flag[NMT];

__device__ __forceinline__ int acq_load(const int* p) {
    int v;
    asm volatile("ld.acquire.gpu.global.b32 %0, [%1];" : "=r"(v) : "l"(p));
    return v;
}

// ===========================================================================
// init: zero mtile flags (runs every call -> graph-replay safe)
// ===========================================================================
__global__ void init_flags_kernel()
{
    if (threadIdx.x < NMT) g_flag[threadIdx.x] = 0;
}

// ===========================================================================
// Transpose w2 [H1][H0] -> w2t [H0][H1]
// ===========================================================================
__global__ void transpose_w2_kernel(const float* __restrict__ w2,
                                    float* __restrict__ w2t)
{
    __shared__ float tile[32][33];
    const int bx = blockIdx.x * 32;
    const int by = blockIdx.y * 32;
    const int tx = threadIdx.x, ty = threadIdx.y;
#pragma unroll
    for (int j = 0; j < 32; j += 8)
        tile[ty + j][tx] = w2[(size_t)(by + ty + j) * H0 + bx + tx];
    __syncthreads();
#pragma unroll
    for (int j = 0; j < 32; j += 8)
        w2t[(size_t)(bx + ty + j) * H1 + by + tx] = tile[tx][ty + j];
}

// ===========================================================================
// Producer body: 64x64 GEMM tile + LIF1 pack epilogue. 128 threads.
// Single-buffered smem; each output's k-chain is sequential (bit == R12).
// ===========================================================================
__device__ __forceinline__ void gemm_body(
    char* sm, int bid,
    const float* __restrict__ A,
    const float* __restrict__ W,
    const float* __restrict__ bias,
    unsigned char* __restrict__ pack)
{
    float* As = reinterpret_cast<float*>(sm);            // [16][64]
    float* Bs = As + 16 * 64;                            // [16][64]

    const int tid = threadIdx.x;
    const int mt  = bid / NTILE;
    const int nt  = bid - mt * NTILE;
    const int m0  = mt * 64;
    const int n0g = nt * 64;

    const int r  = tid >> 2;          // 0..31
    const int c4 = (tid & 3) * 4;

    const int tm = tid >> 4;          // 0..7  (8 rows each)
    const int tn = tid & 15;          // 0..15 (4 cols each)

    unsigned long long acc2[8][2];
#pragma unroll
    for (int i = 0; i < 8; ++i) { acc2[i][0] = 0ull; acc2[i][1] = 0ull; }

    for (int kt = 0; kt < DIN; kt += 16) {
        __syncthreads();
        {
            const float4 a0 = *reinterpret_cast<const float4*>(
                &A[(size_t)(m0 + r) * DIN + kt + c4]);
            const float4 a1 = *reinterpret_cast<const float4*>(
                &A[(size_t)(m0 + r + 32) * DIN + kt + c4]);
            const float4 b0 = *reinterpret_cast<const float4*>(
                &W[(size_t)(n0g + r) * DIN + kt + c4]);
            const float4 b1 = *reinterpret_cast<const float4*>(
                &W[(size_t)(n0g + r + 32) * DIN + kt + c4]);
            As[(c4 + 0) * 64 + r]      = a0.x;
            As[(c4 + 1) * 64 + r]      = a0.y;
            As[(c4 + 2) * 64 + r]      = a0.z;
            As[(c4 + 3) * 64 + r]      = a0.w;
            As[(c4 + 0) * 64 + r + 32] = a1.x;
            As[(c4 + 1) * 64 + r + 32] = a1.y;
            As[(c4 + 2) * 64 + r + 32] = a1.z;
            As[(c4 + 3) * 64 + r + 32] = a1.w;
            Bs[(c4 + 0) * 64 + r]      = b0.x;
            Bs[(c4 + 1) * 64 + r]      = b0.y;
            Bs[(c4 + 2) * 64 + r]      = b0.z;
            Bs[(c4 + 3) * 64 + r]      = b0.w;
            Bs[(c4 + 0) * 64 + r + 32] = b1.x;
            Bs[(c4 + 1) * 64 + r + 32] = b1.y;
            Bs[(c4 + 2) * 64 + r + 32] = b1.z;
            Bs[(c4 + 3) * 64 + r + 32] = b1.w;
        }
        __syncthreads();

#pragma unroll
        for (int k = 0; k < 16; ++k) {
            float a[8];
            unsigned long long b2[2];
            *reinterpret_cast<float4*>(&a[0]) =
                *reinterpret_cast<const float4*>(&As[k * 64 + tm * 8]);
            *reinterpret_cast<float4*>(&a[4]) =
                *reinterpret_cast<const float4*>(&As[k * 64 + tm * 8 + 4]);
            *reinterpret_cast<float4*>(&b2[0]) =
                *reinterpret_cast<const float4*>(&Bs[k * 64 + tn * 4]);
#pragma unroll
            for (int i = 0; i < 8; ++i) {
                unsigned long long a2;
                asm("mov.b64 %0, {%1, %1};" : "=l"(a2) : "f"(a[i]));
                asm("fma.rn.f32x2 %0, %1, %2, %0;"
                    : "+l"(acc2[i][0]) : "l"(a2), "l"(b2[0]));
                asm("fma.rn.f32x2 %0, %1, %2, %0;"
                    : "+l"(acc2[i][1]) : "l"(a2), "l"(b2[1]));
            }
        }
    }

    // epilogue: bias + LIF1 (beta1 = 1.0) -> 4 pattern bytes/row
    const float4 bv = *reinterpret_cast<const float4*>(bias + n0g + tn * 4);
#pragma unroll
    for (int i = 0; i < 8; ++i) {
        float accf[4];
        asm("mov.b64 {%0, %1}, %2;"
            : "=f"(accf[0]), "=f"(accf[1]) : "l"(acc2[i][0]));
        asm("mov.b64 {%0, %1}, %2;"
            : "=f"(accf[2]), "=f"(accf[3]) : "l"(acc2[i][1]));
        const float bj[4] = {bv.x, bv.y, bv.z, bv.w};
        uint32_t u = 0;
#pragma unroll
        for (int j = 0; j < 4; ++j) {
            const float c = accf[j] + bj[j];
            float mem = 0.0f;
            unsigned p = 0;
#pragma unroll
            for (int t = 0; t < T; ++t) {
                const float reset = (mem > 1.0f) ? 1.0f : 0.0f;   // OLD mem
                mem = mem + c - reset;                             // beta1 = 1.0
                p |= ((mem - 1.0f) > 0.0f ? 1u : 0u) << t;
            }
            u |= p << (8 * j);
        }
        const int gm = m0 + tm * 8 + i;
        *reinterpret_cast<uint32_t*>(&pack[(size_t)gm * H0 + n0g + tn * 4]) = u;
    }

    // release this tile
    __threadfence();
    __syncthreads();
    if (tid == 0) atomicAdd(&g_flag[mt], 1);
}

// ===========================================================================
// Consumer body: R12 tail verbatim (spin-gated, pack loaded via ld.cg).
// ===========================================================================
__device__ __forceinline__ void tail_body(
    char* sm, int b,
    const unsigned char* __restrict__ pack,
    const float* __restrict__ w2t,
    const float* __restrict__ b2,
    const float* __restrict__ w3,
    const float* __restrict__ b3,
    float* __restrict__ out)
{
    uint16_t* s_idx     = reinterpret_cast<uint16_t*>(sm);          // 2048 B
    int*      s_wbase   = reinterpret_cast<int*>(sm + 2048);        // [4][256]
    int*      s_start   = reinterpret_cast<int*>(sm + 6144);
    int*      s_cnt     = reinterpret_cast<int*>(sm + 7168);
    int*      s_binlist = reinterpret_cast<int*>(sm + 8192);
    int*      s_w4a     = reinterpret_cast<int*>(sm + 9216);        // [4]
    int*      s_w4b     = reinterpret_cast<int*>(sm + 9232);        // [4]
    int*      s_nbins   = reinterpret_cast<int*>(sm + 9248);
    float*    s_red     = reinterpret_cast<float*>(sm + 9280);      // [4]

    const int tid  = threadIdx.x;
    const int lane = tid & 31;
    const int wid  = tid >> 5;
    const unsigned FULL = 0xFFFFFFFFu;

    // gate on producer mtile (64 rows, 16 tiles)
    if (tid == 0) {
        while (acq_load(&g_flag[b >> 6]) < NTILE) __nanosleep(64);
    }
    __syncthreads();

    uint2 wd;
    asm volatile("ld.global.cg.v2.u32 {%0, %1}, [%2];"
                 : "=r"(wd.x), "=r"(wd.y)
                 : "l"(pack + (size_t)b * H0 + tid * 8));
    uint32_t bytes[8];
#pragma unroll
    for (int j = 0; j < 4; ++j) {
        bytes[j]     = (wd.x >> (8 * j)) & 255u;
        bytes[4 + j] = (wd.y >> (8 * j)) & 255u;
    }

#pragma unroll
    for (int k = 0; k < 8; ++k) {
        const int e = tid * 8 + k;
        s_wbase[(e >> 8) * 256 + (e & 255)] = 0;
    }
    __syncthreads();

#pragma unroll
    for (int j = 0; j < 8; ++j)
        if (bytes[j]) atomicAdd(&s_wbase[wid * 256 + bytes[j]], 1);
    __syncthreads();

    const int p0 = tid * 2, p1 = tid * 2 + 1;
    const int v0 = s_wbase[p0] + s_wbase[256 + p0] + s_wbase[512 + p0] + s_wbase[768 + p0];
    const int v1 = s_wbase[p1] + s_wbase[256 + p1] + s_wbase[512 + p1] + s_wbase[768 + p1];

    {
        int inc = v0 + v1;
#pragma unroll
        for (int d = 1; d < 32; d <<= 1) {
            const int t = __shfl_up_sync(FULL, inc, d);
            if (lane >= d) inc += t;
        }
        if (lane == 31) s_w4a[wid] = inc;
        __syncthreads();
        int woff = 0;
#pragma unroll
        for (int w = 0; w < 4; ++w) woff += (w < wid) ? s_w4a[w] : 0;
        const int e0 = woff + inc - (v0 + v1);
        s_start[p0] = e0;
        s_start[p1] = e0 + v0;
        s_cnt[p0] = v0;
        s_cnt[p1] = v1;
    }

    {
        const int f0 = (p0 != 0 && v0 > 0) ? 1 : 0;
        const int f1 = (v1 > 0) ? 1 : 0;
        int inc = f0 + f1;
#pragma unroll
        for (int d = 1; d < 32; d <<= 1) {
            const int t = __shfl_up_sync(FULL, inc, d);
            if (lane >= d) inc += t;
        }
        if (lane == 31) s_w4b[wid] = inc;
        __syncthreads();
        int woff = 0;
#pragma unroll
        for (int w = 0; w < 4; ++w) woff += (w < wid) ? s_w4b[w] : 0;
        const int c0 = woff + inc - (f0 + f1);
        if (f0) s_binlist[c0] = p0;
        if (f1) s_binlist[c0 + f0] = p1;
        if (tid == 127) *s_nbins = c0 + f0 + f1;
    }
    __syncthreads();

    {
#pragma unroll
        for (int pp = 0; pp < 2; ++pp) {
            const int p = tid * 2 + pp;
            int run = s_start[p];
#pragma unroll
            for (int w = 0; w < 4; ++w) {
                const int t = s_wbase[w * 256 + p];
                s_wbase[w * 256 + p] = run;
                run += t;
            }
        }
    }
    __syncthreads();

#pragma unroll
    for (int j = 0; j < 8; ++j) {
        const uint32_t bj = bytes[j];
        const uint32_t grp = __match_any_sync(FULL, bj);
        const int leader = __ffs(grp) - 1;
        int base = 0;
        if (bj && lane == leader)
            base = atomicAdd(&s_wbase[wid * 256 + bj], __popc(grp));
        base = __shfl_sync(FULL, base, leader);
        if (bj) {
            const int pos = base + __popc(grp & ((1u << lane) - 1u));
            s_idx[pos] = (uint16_t)(tid * 8 + j);
        }
    }
    __syncthreads();

    unsigned long long acc[T][2];
#pragma unroll
    for (int t = 0; t < T; ++t) { acc[t][0] = 0ull; acc[t][1] = 0ull; }

    const char* wbase = reinterpret_cast<const char*>(w2t) + tid * 16;
    const int nbins = *s_nbins;

    for (int bi = 0; bi < nbins; ++bi) {
        const int p  = s_binlist[bi];
        const int st = s_start[p];
        const int en = st + s_cnt[p];

        unsigned long long rs0 = 0ull, rs1 = 0ull;
        int k = st;
        for (; k + 4 <= en; k += 4) {
            const uint32_t i0 = s_idx[k];
            const uint32_t i1 = s_idx[k + 1];
            const uint32_t i2 = s_idx[k + 2];
            const uint32_t i3 = s_idx[k + 3];
            unsigned long long a0, b0, a1, b1, a2, b2, a3, b3;
            asm("ld.global.nc.L1::evict_last.v2.u64 {%0, %1}, [%2];"
                : "=l"(a0), "=l"(b0) : "l"(wbase + (size_t)i0 * (H1 * 4)));
            asm("ld.global.nc.L1::evict_last.v2.u64 {%0, %1}, [%2];"
                : "=l"(a1), "=l"(b1) : "l"(wbase + (size_t)i1 * (H1 * 4)));
            asm("ld.global.nc.L1::evict_last.v2.u64 {%0, %1}, [%2];"
                : "=l"(a2), "=l"(b2) : "l"(wbase + (size_t)i2 * (H1 * 4)));
            asm("ld.global.nc.L1::evict_last.v2.u64 {%0, %1}, [%2];"
                : "=l"(a3), "=l"(b3) : "l"(wbase + (size_t)i3 * (H1 * 4)));
            asm("add.rn.f32x2 %0, %0, %1;" : "+l"(rs0) : "l"(a0));
            asm("add.rn.f32x2 %0, %0, %1;" : "+l"(rs1) : "l"(b0));
            asm("add.rn.f32x2 %0, %0, %1;" : "+l"(rs0) : "l"(a1));
            asm("add.rn.f32x2 %0, %0, %1;" : "+l"(rs1) : "l"(b1));
            asm("add.rn.f32x2 %0, %0, %1;" : "+l"(rs0) : "l"(a2));
            asm("add.rn.f32x2 %0, %0, %1;" : "+l"(rs1) : "l"(b2));
            asm("add.rn.f32x2 %0, %0, %1;" : "+l"(rs0) : "l"(a3));
            asm("add.rn.f32x2 %0, %0, %1;" : "+l"(rs1) : "l"(b3));
        }
        for (; k < en; ++k) {
            const uint32_t i = s_idx[k];
            unsigned long long w01, w23;
            asm("ld.global.nc.L1::evict_last.v2.u64 {%0, %1}, [%2];"
                : "=l"(w01), "=l"(w23)
                : "l"(wbase + (size_t)i * (H1 * 4)));
            asm("add.rn.f32x2 %0, %0, %1;" : "+l"(rs0) : "l"(w01));
            asm("add.rn.f32x2 %0, %0, %1;" : "+l"(rs1) : "l"(w23));
        }

#pragma unroll
        for (int t = 0; t < T; ++t) {
            asm("{ .reg .pred q;\n\t"
                "setp.ne.u32 q, %4, 0;\n\t"
                "@q add.rn.f32x2 %0, %0, %2;\n\t"
                "@q add.rn.f32x2 %1, %1, %3; }"
                : "+l"(acc[t][0]), "+l"(acc[t][1])
                : "l"(rs0), "l"(rs1), "r"((unsigned)p & (1u << t)));
        }
    }

    const int n0 = tid * 4;
    const float4 b2v = *reinterpret_cast<const float4*>(b2 + n0);
    const float4 w3v = *reinterpret_cast<const float4*>(w3 + n0);
    float m0 = 0.0f, m1 = 0.0f, m2 = 0.0f, m3 = 0.0f, aout = 0.0f;
#pragma unroll
    for (int t = 0; t < T; ++t) {
        float a0, a1, a2, a3;
        asm("mov.b64 {%0, %1}, %2;" : "=f"(a0), "=f"(a1) : "l"(acc[t][0]));
        asm("mov.b64 {%0, %1}, %2;" : "=f"(a2), "=f"(a3) : "l"(acc[t][1]));
        const float c0 = a0 + b2v.x, c1 = a1 + b2v.y;
        const float c2 = a2 + b2v.z, c3 = a3 + b2v.w;
        const float r0 = (m0 > 1.0f) ? 1.0f : 0.0f;   // reset on OLD mem
        const float r1 = (m1 > 1.0f) ? 1.0f : 0.0f;
        const float r2 = (m2 > 1.0f) ? 1.0f : 0.0f;
        const float r3 = (m3 > 1.0f) ? 1.0f : 0.0f;
        m0 = 0.95f * m0 + c0 - r0;
        m1 = 0.95f * m1 + c1 - r1;
        m2 = 0.95f * m2 + c2 - r2;
        m3 = 0.95f * m3 + c3 - r3;
        aout += ((m0 - 1.0f) > 0.0f) ? w3v.x : 0.0f;
        aout += ((m1 - 1.0f) > 0.0f) ? w3v.y : 0.0f;
        aout += ((m2 - 1.0f) > 0.0f) ? w3v.z : 0.0f;
        aout += ((m3 - 1.0f) > 0.0f) ? w3v.w : 0.0f;
    }

#pragma unroll
    for (int d = 16; d > 0; d >>= 1)
        aout += __shfl_down_sync(FULL, aout, d);
    if (lane == 0) s_red[wid] = aout;
    __syncthreads();
    if (tid == 0) {
        out[b] = (s_red[0] + s_red[1] + s_red[2] + s_red[3]) * (1.0f / T)
               + __ldg(&b3[0]);
    }
}

// ===========================================================================
// Fused kernel
// ===========================================================================
__global__ void __launch_bounds__(128, 6) snn_fused_kernel(
    const float* __restrict__ data,
    const float* __restrict__ w1,
    const float* __restrict__ b1,
    unsigned char* __restrict__ pack,
    const float* __restrict__ w2t,
    const float* __restrict__ b2,
    const float* __restrict__ w3,
    const float* __restrict__ b3,
    float* __restrict__ out)
{
    extern __shared__ char sm[];
    const int bid = blockIdx.x;
    if (bid < NGEMM) {
        gemm_body(sm, bid, data, w1, b1, pack);
    } else {
        tail_body(sm, bid - NGEMM, pack, w2t, b2, w3, b3, out);
    }
}

// ---------------------------------------------------------------------------
extern "C" void kernel_launch(void* const* d_in, const int* in_sizes, int n_in,
                              void* d_out, int out_size)
{
    const float* data = (const float*)d_in[0];
    const float* w1   = (const float*)d_in[1];
    const float* b1   = (const float*)d_in[2];
    const float* w2   = (const float*)d_in[3];
    const float* b2   = (const float*)d_in[4];
    const float* w3   = (const float*)d_in[5];
    const float* b3   = (const float*)d_in[6];
    float* out = (float*)d_out;

    unsigned char* pack;
    float* w2t;
    cudaGetSymbolAddress((void**)&pack, g_pack);
    cudaGetSymbolAddress((void**)&w2t,  g_w2t);

    // 1) zero producer flags (every call -> replay-safe)
    init_flags_kernel<<<1, 256>>>();

    // 2) transpose w2 -> w2t [H0][H1]
    {
        dim3 grid(H0 / 32, H1 / 32);
        transpose_w2_kernel<<<grid, dim3(32, 8)>>>(w2, w2t);
    }

    // 3) fused GEMM1+pack producers followed (in bid order) by tail consumers
    snn_fused_kernel<<<NGEMM + BB, 128, SMEM_DYN>>>(
        data, w1, b1, pack, w2t, b2, w3, b3, out);
}

// round 17
// speedup vs baseline: 3.0090x; 1.0235x over previous
#include <cuda_runtime.h>
#include <cstdint>
#include <cstddef>

// ---------------------------------------------------------------------------
// SNN forward, fused producer/consumer (R16 structure, producer fixed):
//   blocks [0, 4096):  GEMM1 64x64 tiles, DOUBLE-BUFFERED (R12 scheme:
//                      reg-prefetch next k-tile during compute, 1 barrier/it)
//                      + LIF1 pack epilogue. Per-element FMA chain k-ascending
//                      -> cur1 / pack bytes bit-identical to R12.
//   blocks [4096, ...): R12 tail verbatim, gated per 64-row mtile by flags.
//   R16 post-mortem: overlap worked, but the single-buffered producer's
//   aggregate (~650us) equaled the tail -> no net win. This round halves
//   producer latency exposure.
// ---------------------------------------------------------------------------

static constexpr int BB  = 16384;
static constexpr int DIN = 512;
static constexpr int H0  = 1024;
static constexpr int H1  = 512;
static constexpr int T   = 8;

static constexpr int NMT      = 256;              // mtiles of 64 rows
static constexpr int NTILE    = 16;               // 64-col tiles in H0
static constexpr int NGEMM    = NMT * NTILE;      // 4096 producer blocks
static constexpr int SMEM_DYN = 16384;            // gemm 2x8KB; tail ~9.3KB

// Scratch (device globals -- no runtime allocation allowed)
__device__ __align__(256) unsigned char g_pack[(size_t)BB * H0];  // 16 MB
__device__ __align__(256) float         g_w2t [(size_t)H0 * H1]; //  2 MB
__device__                int           g_flag[NMT];

__device__ __forceinline__ int acq_load(const int* p) {
    int v;
    asm volatile("ld.acquire.gpu.global.b32 %0, [%1];" : "=r"(v) : "l"(p));
    return v;
}

// ===========================================================================
// init: zero mtile flags (runs every call -> graph-replay safe)
// ===========================================================================
__global__ void init_flags_kernel()
{
    if (threadIdx.x < NMT) g_flag[threadIdx.x] = 0;
}

// ===========================================================================
// Transpose w2 [H1][H0] -> w2t [H0][H1]
// ===========================================================================
__global__ void transpose_w2_kernel(const float* __restrict__ w2,
                                    float* __restrict__ w2t)
{
    __shared__ float tile[32][33];
    const int bx = blockIdx.x * 32;
    const int by = blockIdx.y * 32;
    const int tx = threadIdx.x, ty = threadIdx.y;
#pragma unroll
    for (int j = 0; j < 32; j += 8)
        tile[ty + j][tx] = w2[(size_t)(by + ty + j) * H0 + bx + tx];
    __syncthreads();
#pragma unroll
    for (int j = 0; j < 32; j += 8)
        w2t[(size_t)(bx + ty + j) * H1 + by + tx] = tile[tx][ty + j];
}

// ===========================================================================
// Producer body: 64x64 GEMM tile, double-buffered, + LIF1 pack epilogue.
// 128 threads; thread owns 8 rows x 4 cols.
// ===========================================================================
__device__ __forceinline__ void gemm_body(
    char* sm, int bid,
    const float* __restrict__ A,
    const float* __restrict__ W,
    const float* __restrict__ bias,
    unsigned char* __restrict__ pack)
{
    float* As = reinterpret_cast<float*>(sm);        // [2][16][64]
    float* Bs = As + 2 * 16 * 64;                    // [2][16][64]

    const int tid = threadIdx.x;
    const int mt  = bid / NTILE;
    const int nt  = bid - mt * NTILE;
    const int m0  = mt * 64;
    const int n0g = nt * 64;

    const int r  = tid >> 2;          // 0..31
    const int c4 = (tid & 3) * 4;

    const int tm = tid >> 4;          // 0..7  (8 rows each)
    const int tn = tid & 15;          // 0..15 (4 cols each)

    unsigned long long acc2[8][2];
#pragma unroll
    for (int i = 0; i < 8; ++i) { acc2[i][0] = 0ull; acc2[i][1] = 0ull; }

    float4 ra0, ra1, rb0, rb1;

    auto load_regs = [&](int kt) {
        ra0 = *reinterpret_cast<const float4*>(&A[(size_t)(m0 + r) * DIN + kt + c4]);
        ra1 = *reinterpret_cast<const float4*>(&A[(size_t)(m0 + r + 32) * DIN + kt + c4]);
        rb0 = *reinterpret_cast<const float4*>(&W[(size_t)(n0g + r) * DIN + kt + c4]);
        rb1 = *reinterpret_cast<const float4*>(&W[(size_t)(n0g + r + 32) * DIN + kt + c4]);
    };
    auto store_smem = [&](int buf) {
        float* as = As + buf * 16 * 64;
        float* bs = Bs + buf * 16 * 64;
        as[(c4 + 0) * 64 + r]      = ra0.x;
        as[(c4 + 1) * 64 + r]      = ra0.y;
        as[(c4 + 2) * 64 + r]      = ra0.z;
        as[(c4 + 3) * 64 + r]      = ra0.w;
        as[(c4 + 0) * 64 + r + 32] = ra1.x;
        as[(c4 + 1) * 64 + r + 32] = ra1.y;
        as[(c4 + 2) * 64 + r + 32] = ra1.z;
        as[(c4 + 3) * 64 + r + 32] = ra1.w;
        bs[(c4 + 0) * 64 + r]      = rb0.x;
        bs[(c4 + 1) * 64 + r]      = rb0.y;
        bs[(c4 + 2) * 64 + r]      = rb0.z;
        bs[(c4 + 3) * 64 + r]      = rb0.w;
        bs[(c4 + 0) * 64 + r + 32] = rb1.x;
        bs[(c4 + 1) * 64 + r + 32] = rb1.y;
        bs[(c4 + 2) * 64 + r + 32] = rb1.z;
        bs[(c4 + 3) * 64 + r + 32] = rb1.w;
    };

    load_regs(0);
    store_smem(0);
    __syncthreads();

    const int nt_it = DIN / 16;       // 32
    for (int it = 0; it < nt_it; ++it) {
        const int buf = it & 1;
        const bool more = (it + 1 < nt_it);
        if (more) load_regs((it + 1) * 16);    // overlap with compute

        const float* as = As + buf * 16 * 64;
        const float* bs = Bs + buf * 16 * 64;
#pragma unroll
        for (int k = 0; k < 16; ++k) {
            float a[8];
            unsigned long long b2[2];
            *reinterpret_cast<float4*>(&a[0]) =
                *reinterpret_cast<const float4*>(&as[k * 64 + tm * 8]);
            *reinterpret_cast<float4*>(&a[4]) =
                *reinterpret_cast<const float4*>(&as[k * 64 + tm * 8 + 4]);
            *reinterpret_cast<float4*>(&b2[0]) =
                *reinterpret_cast<const float4*>(&bs[k * 64 + tn * 4]);
#pragma unroll
            for (int i = 0; i < 8; ++i) {
                unsigned long long a2;
                asm("mov.b64 %0, {%1, %1};" : "=l"(a2) : "f"(a[i]));
                asm("fma.rn.f32x2 %0, %1, %2, %0;"
                    : "+l"(acc2[i][0]) : "l"(a2), "l"(b2[0]));
                asm("fma.rn.f32x2 %0, %1, %2, %0;"
                    : "+l"(acc2[i][1]) : "l"(a2), "l"(b2[1]));
            }
        }

        if (more) {
            store_smem(buf ^ 1);   // buf^1 fully consumed before prev barrier
            __syncthreads();
        }
    }

    // epilogue: bias + LIF1 (beta1 = 1.0) -> 4 pattern bytes/row
    const float4 bv = *reinterpret_cast<const float4*>(bias + n0g + tn * 4);
#pragma unroll
    for (int i = 0; i < 8; ++i) {
        float accf[4];
        asm("mov.b64 {%0, %1}, %2;"
            : "=f"(accf[0]), "=f"(accf[1]) : "l"(acc2[i][0]));
        asm("mov.b64 {%0, %1}, %2;"
            : "=f"(accf[2]), "=f"(accf[3]) : "l"(acc2[i][1]));
        const float bj[4] = {bv.x, bv.y, bv.z, bv.w};
        uint32_t u = 0;
#pragma unroll
        for (int j = 0; j < 4; ++j) {
            const float c = accf[j] + bj[j];
            float mem = 0.0f;
            unsigned p = 0;
#pragma unroll
            for (int t = 0; t < T; ++t) {
                const float reset = (mem > 1.0f) ? 1.0f : 0.0f;   // OLD mem
                mem = mem + c - reset;                             // beta1 = 1.0
                p |= ((mem - 1.0f) > 0.0f ? 1u : 0u) << t;
            }
            u |= p << (8 * j);
        }
        const int gm = m0 + tm * 8 + i;
        *reinterpret_cast<uint32_t*>(&pack[(size_t)gm * H0 + n0g + tn * 4]) = u;
    }

    // release this tile
    __threadfence();
    __syncthreads();
    if (tid == 0) atomicAdd(&g_flag[mt], 1);
}

// ===========================================================================
// Consumer body: R12 tail verbatim (spin-gated, pack loaded via ld.cg).
// ===========================================================================
__device__ __forceinline__ void tail_body(
    char* sm, int b,
    const unsigned char* __restrict__ pack,
    const float* __restrict__ w2t,
    const float* __restrict__ b2,
    const float* __restrict__ w3,
    const float* __restrict__ b3,
    float* __restrict__ out)
{
    uint16_t* s_idx     = reinterpret_cast<uint16_t*>(sm);          // 2048 B
    int*      s_wbase   = reinterpret_cast<int*>(sm + 2048);        // [4][256]
    int*      s_start   = reinterpret_cast<int*>(sm + 6144);
    int*      s_cnt     = reinterpret_cast<int*>(sm + 7168);
    int*      s_binlist = reinterpret_cast<int*>(sm + 8192);
    int*      s_w4a     = reinterpret_cast<int*>(sm + 9216);        // [4]
    int*      s_w4b     = reinterpret_cast<int*>(sm + 9232);        // [4]
    int*      s_nbins   = reinterpret_cast<int*>(sm + 9248);
    float*    s_red     = reinterpret_cast<float*>(sm + 9280);      // [4]

    const int tid  = threadIdx.x;
    const int lane = tid & 31;
    const int wid  = tid >> 5;
    const unsigned FULL = 0xFFFFFFFFu;

    // gate on producer mtile (64 rows, 16 tiles)
    if (tid == 0) {
        while (acq_load(&g_flag[b >> 6]) < NTILE) __nanosleep(64);
    }
    __syncthreads();

    uint2 wd;
    asm volatile("ld.global.cg.v2.u32 {%0, %1}, [%2];"
                 : "=r"(wd.x), "=r"(wd.y)
                 : "l"(pack + (size_t)b * H0 + tid * 8));
    uint32_t bytes[8];
#pragma unroll
    for (int j = 0; j < 4; ++j) {
        bytes[j]     = (wd.x >> (8 * j)) & 255u;
        bytes[4 + j] = (wd.y >> (8 * j)) & 255u;
    }

#pragma unroll
    for (int k = 0; k < 8; ++k) {
        const int e = tid * 8 + k;
        s_wbase[(e >> 8) * 256 + (e & 255)] = 0;
    }
    __syncthreads();

#pragma unroll
    for (int j = 0; j < 8; ++j)
        if (bytes[j]) atomicAdd(&s_wbase[wid * 256 + bytes[j]], 1);
    __syncthreads();

    const int p0 = tid * 2, p1 = tid * 2 + 1;
    const int v0 = s_wbase[p0] + s_wbase[256 + p0] + s_wbase[512 + p0] + s_wbase[768 + p0];
    const int v1 = s_wbase[p1] + s_wbase[256 + p1] + s_wbase[512 + p1] + s_wbase[768 + p1];

    {
        int inc = v0 + v1;
#pragma unroll
        for (int d = 1; d < 32; d <<= 1) {
            const int t = __shfl_up_sync(FULL, inc, d);
            if (lane >= d) inc += t;
        }
        if (lane == 31) s_w4a[wid] = inc;
        __syncthreads();
        int woff = 0;
#pragma unroll
        for (int w = 0; w < 4; ++w) woff += (w < wid) ? s_w4a[w] : 0;
        const int e0 = woff + inc - (v0 + v1);
        s_start[p0] = e0;
        s_start[p1] = e0 + v0;
        s_cnt[p0] = v0;
        s_cnt[p1] = v1;
    }

    {
        const int f0 = (p0 != 0 && v0 > 0) ? 1 : 0;
        const int f1 = (v1 > 0) ? 1 : 0;
        int inc = f0 + f1;
#pragma unroll
        for (int d = 1; d < 32; d <<= 1) {
            const int t = __shfl_up_sync(FULL, inc, d);
            if (lane >= d) inc += t;
        }
        if (lane == 31) s_w4b[wid] = inc;
        __syncthreads();
        int woff = 0;
#pragma unroll
        for (int w = 0; w < 4; ++w) woff += (w < wid) ? s_w4b[w] : 0;
        const int c0 = woff + inc - (f0 + f1);
        if (f0) s_binlist[c0] = p0;
        if (f1) s_binlist[c0 + f0] = p1;
        if (tid == 127) *s_nbins = c0 + f0 + f1;
    }
    __syncthreads();

    {
#pragma unroll
        for (int pp = 0; pp < 2; ++pp) {
            const int p = tid * 2 + pp;
            int run = s_start[p];
#pragma unroll
            for (int w = 0; w < 4; ++w) {
                const int t = s_wbase[w * 256 + p];
                s_wbase[w * 256 + p] = run;
                run += t;
            }
        }
    }
    __syncthreads();

#pragma unroll
    for (int j = 0; j < 8; ++j) {
        const uint32_t bj = bytes[j];
        const uint32_t grp = __match_any_sync(FULL, bj);
        const int leader = __ffs(grp) - 1;
        int base = 0;
        if (bj && lane == leader)
            base = atomicAdd(&s_wbase[wid * 256 + bj], __popc(grp));
        base = __shfl_sync(FULL, base, leader);
        if (bj) {
            const int pos = base + __popc(grp & ((1u << lane) - 1u));
            s_idx[pos] = (uint16_t)(tid * 8 + j);
        }
    }
    __syncthreads();

    unsigned long long acc[T][2];
#pragma unroll
    for (int t = 0; t < T; ++t) { acc[t][0] = 0ull; acc[t][1] = 0ull; }

    const char* wbase = reinterpret_cast<const char*>(w2t) + tid * 16;
    const int nbins = *s_nbins;

    for (int bi = 0; bi < nbins; ++bi) {
        const int p  = s_binlist[bi];
        const int st = s_start[p];
        const int en = st + s_cnt[p];

        unsigned long long rs0 = 0ull, rs1 = 0ull;
        int k = st;
        for (; k + 4 <= en; k += 4) {
            const uint32_t i0 = s_idx[k];
            const uint32_t i1 = s_idx[k + 1];
            const uint32_t i2 = s_idx[k + 2];
            const uint32_t i3 = s_idx[k + 3];
            unsigned long long a0, b0, a1, b1, a2, b2, a3, b3;
            asm("ld.global.nc.L1::evict_last.v2.u64 {%0, %1}, [%2];"
                : "=l"(a0), "=l"(b0) : "l"(wbase + (size_t)i0 * (H1 * 4)));
            asm("ld.global.nc.L1::evict_last.v2.u64 {%0, %1}, [%2];"
                : "=l"(a1), "=l"(b1) : "l"(wbase + (size_t)i1 * (H1 * 4)));
            asm("ld.global.nc.L1::evict_last.v2.u64 {%0, %1}, [%2];"
                : "=l"(a2), "=l"(b2) : "l"(wbase + (size_t)i2 * (H1 * 4)));
            asm("ld.global.nc.L1::evict_last.v2.u64 {%0, %1}, [%2];"
                : "=l"(a3), "=l"(b3) : "l"(wbase + (size_t)i3 * (H1 * 4)));
            asm("add.rn.f32x2 %0, %0, %1;" : "+l"(rs0) : "l"(a0));
            asm("add.rn.f32x2 %0, %0, %1;" : "+l"(rs1) : "l"(b0));
            asm("add.rn.f32x2 %0, %0, %1;" : "+l"(rs0) : "l"(a1));
            asm("add.rn.f32x2 %0, %0, %1;" : "+l"(rs1) : "l"(b1));
            asm("add.rn.f32x2 %0, %0, %1;" : "+l"(rs0) : "l"(a2));
            asm("add.rn.f32x2 %0, %0, %1;" : "+l"(rs1) : "l"(b2));
            asm("add.rn.f32x2 %0, %0, %1;" : "+l"(rs0) : "l"(a3));
            asm("add.rn.f32x2 %0, %0, %1;" : "+l"(rs1) : "l"(b3));
        }
        for (; k < en; ++k) {
            const uint32_t i = s_idx[k];
            unsigned long long w01, w23;
            asm("ld.global.nc.L1::evict_last.v2.u64 {%0, %1}, [%2];"
                : "=l"(w01), "=l"(w23)
                : "l"(wbase + (size_t)i * (H1 * 4)));
            asm("add.rn.f32x2 %0, %0, %1;" : "+l"(rs0) : "l"(w01));
            asm("add.rn.f32x2 %0, %0, %1;" : "+l"(rs1) : "l"(w23));
        }

#pragma unroll
        for (int t = 0; t < T; ++t) {
            asm("{ .reg .pred q;\n\t"
                "setp.ne.u32 q, %4, 0;\n\t"
                "@q add.rn.f32x2 %0, %0, %2;\n\t"
                "@q add.rn.f32x2 %1, %1, %3; }"
                : "+l"(acc[t][0]), "+l"(acc[t][1])
                : "l"(rs0), "l"(rs1), "r"((unsigned)p & (1u << t)));
        }
    }

    const int n0 = tid * 4;
    const float4 b2v = *reinterpret_cast<const float4*>(b2 + n0);
    const float4 w3v = *reinterpret_cast<const float4*>(w3 + n0);
    float m0 = 0.0f, m1 = 0.0f, m2 = 0.0f, m3 = 0.0f, aout = 0.0f;
#pragma unroll
    for (int t = 0; t < T; ++t) {
        float a0, a1, a2, a3;
        asm("mov.b64 {%0, %1}, %2;" : "=f"(a0), "=f"(a1) : "l"(acc[t][0]));
        asm("mov.b64 {%0, %1}, %2;" : "=f"(a2), "=f"(a3) : "l"(acc[t][1]));
        const float c0 = a0 + b2v.x, c1 = a1 + b2v.y;
        const float c2 = a2 + b2v.z, c3 = a3 + b2v.w;
        const float r0 = (m0 > 1.0f) ? 1.0f : 0.0f;   // reset on OLD mem
        const float r1 = (m1 > 1.0f) ? 1.0f : 0.0f;
        const float r2 = (m2 > 1.0f) ? 1.0f : 0.0f;
        const float r3 = (m3 > 1.0f) ? 1.0f : 0.0f;
        m0 = 0.95f * m0 + c0 - r0;
        m1 = 0.95f * m1 + c1 - r1;
        m2 = 0.95f * m2 + c2 - r2;
        m3 = 0.95f * m3 + c3 - r3;
        aout += ((m0 - 1.0f) > 0.0f) ? w3v.x : 0.0f;
        aout += ((m1 - 1.0f) > 0.0f) ? w3v.y : 0.0f;
        aout += ((m2 - 1.0f) > 0.0f) ? w3v.z : 0.0f;
        aout += ((m3 - 1.0f) > 0.0f) ? w3v.w : 0.0f;
    }

#pragma unroll
    for (int d = 16; d > 0; d >>= 1)
        aout += __shfl_down_sync(FULL, aout, d);
    if (lane == 0) s_red[wid] = aout;
    __syncthreads();
    if (tid == 0) {
        out[b] = (s_red[0] + s_red[1] + s_red[2] + s_red[3]) * (1.0f / T)
               + __ldg(&b3[0]);
    }
}

// ===========================================================================
// Fused kernel
// ===========================================================================
__global__ void __launch_bounds__(128, 6) snn_fused_kernel(
    const float* __restrict__ data,
    const float* __restrict__ w1,
    const float* __restrict__ b1,
    unsigned char* __restrict__ pack,
    const float* __restrict__ w2t,
    const float* __restrict__ b2,
    const float* __restrict__ w3,
    const float* __restrict__ b3,
    float* __restrict__ out)
{
    extern __shared__ char sm[];
    const int bid = blockIdx.x;
    if (bid < NGEMM) {
        gemm_body(sm, bid, data, w1, b1, pack);
    } else {
        tail_body(sm, bid - NGEMM, pack, w2t, b2, w3, b3, out);
    }
}

// ---------------------------------------------------------------------------
extern "C" void kernel_launch(void* const* d_in, const int* in_sizes, int n_in,
                              void* d_out, int out_size)
{
    const float* data = (const float*)d_in[0];
    const float* w1   = (const float*)d_in[1];
    const float* b1   = (const float*)d_in[2];
    const float* w2   = (const float*)d_in[3];
    const float* b2   = (const float*)d_in[4];
    const float* w3   = (const float*)d_in[5];
    const float* b3   = (const float*)d_in[6];
    float* out = (float*)d_out;

    unsigned char* pack;
    float* w2t;
    cudaGetSymbolAddress((void**)&pack, g_pack);
    cudaGetSymbolAddress((void**)&w2t,  g_w2t);

    // 1) zero producer flags (every call -> replay-safe)
    init_flags_kernel<<<1, 256>>>();

    // 2) transpose w2 -> w2t [H0][H1]
    {
        dim3 grid(H0 / 32, H1 / 32);
        transpose_w2_kernel<<<grid, dim3(32, 8)>>>(w2, w2t);
    }

    // 3) fused GEMM1+pack producers followed (in bid order) by tail consumers
    snn_fused_kernel<<<NGEMM + BB, 128, SMEM_DYN>>>(
        data, w1, b1, pack, w2t, b2, w3, b3, out);
}